// round 1
// baseline (speedup 1.0000x reference)
#include <cuda_runtime.h>

// out[m][n] = C[m][n] * D[n];  M = NR = 8192, row-major.
// Pure HBM-streaming: 512 MB total traffic -> ~70-90 us at ~7 TB/s.

static constexpr int NR   = 8192;
static constexpr int NR4  = NR / 4;          // 2048 float4 columns
static constexpr long long TOTAL4 = (long long)8192 * NR4;  // 16,777,216 float4 elems

__global__ __launch_bounds__(256)
void colscale_kernel(const float4* __restrict__ C,
                     const float4* __restrict__ D,
                     float4* __restrict__ out)
{
    // Each thread processes 4 float4s per grid-stride iteration (MLP=4).
    long long stride = (long long)gridDim.x * blockDim.x;
    long long i = (long long)blockIdx.x * blockDim.x + threadIdx.x;

    for (; i + 3 * stride < TOTAL4; i += 4 * stride) {
        long long i0 = i;
        long long i1 = i + stride;
        long long i2 = i + 2 * stride;
        long long i3 = i + 3 * stride;

        float4 c0 = C[i0];
        float4 c1 = C[i1];
        float4 c2 = C[i2];
        float4 c3 = C[i3];

        float4 d0 = __ldg(&D[(int)(i0 & (NR4 - 1))]);
        float4 d1 = __ldg(&D[(int)(i1 & (NR4 - 1))]);
        float4 d2 = __ldg(&D[(int)(i2 & (NR4 - 1))]);
        float4 d3 = __ldg(&D[(int)(i3 & (NR4 - 1))]);

        float4 o0 = make_float4(c0.x * d0.x, c0.y * d0.y, c0.z * d0.z, c0.w * d0.w);
        float4 o1 = make_float4(c1.x * d1.x, c1.y * d1.y, c1.z * d1.z, c1.w * d1.w);
        float4 o2 = make_float4(c2.x * d2.x, c2.y * d2.y, c2.z * d2.z, c2.w * d2.w);
        float4 o3 = make_float4(c3.x * d3.x, c3.y * d3.y, c3.z * d3.z, c3.w * d3.w);

        out[i0] = o0;
        out[i1] = o1;
        out[i2] = o2;
        out[i3] = o3;
    }
    // Tail (exact multiple here, but keep it correct for safety).
    for (; i < TOTAL4; i += stride) {
        float4 c = C[i];
        float4 d = __ldg(&D[(int)(i & (NR4 - 1))]);
        out[i] = make_float4(c.x * d.x, c.y * d.y, c.z * d.z, c.w * d.w);
    }
}

extern "C" void kernel_launch(void* const* d_in, const int* in_sizes, int n_in,
                              void* d_out, int out_size)
{
    const float4* C = (const float4*)d_in[0];
    const float4* D = (const float4*)d_in[1];
    float4* out     = (float4*)d_out;

    // 16.7M float4s / (4 per thread per iter). 148 SMs; pick a grid that gives
    // one grid-stride iteration for most threads: 16384 blocks x 256 thr x 4 = 16.7M.
    dim3 block(256);
    dim3 grid(16384);
    colscale_kernel<<<grid, block>>>(C, D, out);
}